// round 2
// baseline (speedup 1.0000x reference)
#include <cuda_runtime.h>
#include <cstdint>

// out[m,n] = relu( sum_k x[m,k] * W[n,k] + b[n] )
// M=131072, N=256, K=256, all fp32.
// tf32 warp-level mma.sync, BM=128 BN=128 BK=32, cp.async double buffer.

#define BM 128
#define BN 128
#define BK 32
#define LDA 36  // padded float stride: 144B, 16B-aligned, conflict-free for frag loads
#define LDB 36
#define KDIM 256
#define SMEM_BYTES ((2 * BM * LDA + 2 * BN * LDB) * 4)

__device__ __forceinline__ uint32_t f2tf32(float f) {
    uint32_t r;
    asm("cvt.rna.tf32.f32 %0, %1;" : "=r"(r) : "f"(f));
    return r;
}

__global__ void __launch_bounds__(256, 2)
gemm_tf32_relu(const float* __restrict__ X, const float* __restrict__ Wt,
               const float* __restrict__ bias, float* __restrict__ Out)
{
    extern __shared__ float smem[];
    float* As = smem;                 // 2 * BM * LDA floats
    float* Bs = smem + 2 * BM * LDA;  // 2 * BN * LDB floats

    const int tid  = threadIdx.x;
    const int lane = tid & 31;
    const int warp = tid >> 5;
    const int warpM = warp & 3;   // 0..3 -> 32-row M slice
    const int warpN = warp >> 2;  // 0..1 -> 64-col N slice

    const int ctaM = blockIdx.x * BM;
    const int ctaN = blockIdx.y * BN;

    const int r = lane >> 2;  // 0..7
    const int c = lane & 3;   // 0..3

    float acc[2][8][4];
#pragma unroll
    for (int i = 0; i < 2; i++)
#pragma unroll
        for (int j = 0; j < 8; j++)
#pragma unroll
            for (int q = 0; q < 4; q++) acc[i][j][q] = 0.0f;

    // --- async tile loader: chunk kk (k = kk*BK) into buffer buf ---
    auto issue = [&](int kk, int buf) {
        const float* gA = X + (size_t)ctaM * KDIM + kk * BK;
        const float* gB = Wt + (size_t)ctaN * KDIM + kk * BK;
#pragma unroll
        for (int i = 0; i < 4; i++) {
            int s   = tid + i * 256;   // 0..1023 float4 slots (128 rows x 8 f4)
            int row = s >> 3;
            int c4  = (s & 7) << 2;
            uint32_t dA = (uint32_t)__cvta_generic_to_shared(
                &As[buf * BM * LDA + row * LDA + c4]);
            asm volatile("cp.async.cg.shared.global [%0], [%1], 16;\n"
                         :: "r"(dA), "l"(gA + (size_t)row * KDIM + c4));
            uint32_t dB = (uint32_t)__cvta_generic_to_shared(
                &Bs[buf * BN * LDB + row * LDB + c4]);
            asm volatile("cp.async.cg.shared.global [%0], [%1], 16;\n"
                         :: "r"(dB), "l"(gB + (size_t)row * KDIM + c4));
        }
    };

    auto compute = [&](int buf) {
        const float* A0 = &As[buf * BM * LDA + (warpM * 32) * LDA];
        const float* B0 = &Bs[buf * BN * LDB + (warpN * 64) * LDB];
#pragma unroll
        for (int ks = 0; ks < 4; ks++) {
            const int kb = ks * 8;
            uint32_t a[2][4];
#pragma unroll
            for (int mt = 0; mt < 2; mt++) {
                const float* ap = A0 + (mt * 16 + r) * LDA + kb + c;
                a[mt][0] = f2tf32(ap[0]);
                a[mt][1] = f2tf32(ap[8 * LDA]);
                a[mt][2] = f2tf32(ap[4]);
                a[mt][3] = f2tf32(ap[8 * LDA + 4]);
            }
#pragma unroll
            for (int nt = 0; nt < 8; nt++) {
                const float* bp = B0 + (nt * 8 + r) * LDB + kb + c;
                uint32_t b0 = f2tf32(bp[0]);
                uint32_t b1 = f2tf32(bp[4]);
#pragma unroll
                for (int mt = 0; mt < 2; mt++) {
                    asm volatile(
                        "mma.sync.aligned.m16n8k8.row.col.f32.tf32.tf32.f32 "
                        "{%0,%1,%2,%3}, {%4,%5,%6,%7}, {%8,%9}, {%0,%1,%2,%3};\n"
                        : "+f"(acc[mt][nt][0]), "+f"(acc[mt][nt][1]),
                          "+f"(acc[mt][nt][2]), "+f"(acc[mt][nt][3])
                        : "r"(a[mt][0]), "r"(a[mt][1]), "r"(a[mt][2]), "r"(a[mt][3]),
                          "r"(b0), "r"(b1));
                }
            }
        }
    };

    // --- pipelined mainloop: 8 K-chunks, double buffered ---
    issue(0, 0);
    asm volatile("cp.async.commit_group;\n" ::: "memory");
#pragma unroll 1
    for (int kk = 0; kk < KDIM / BK; ++kk) {
        if (kk + 1 < KDIM / BK) {
            issue(kk + 1, (kk + 1) & 1);
            asm volatile("cp.async.commit_group;\n" ::: "memory");
            asm volatile("cp.async.wait_group 1;\n" ::: "memory");
        } else {
            asm volatile("cp.async.wait_group 0;\n" ::: "memory");
        }
        __syncthreads();
        compute(kk & 1);
        __syncthreads();
    }

    // --- epilogue: bias + relu, float2 stores ---
#pragma unroll
    for (int mt = 0; mt < 2; mt++) {
        const int m0 = ctaM + warpM * 32 + mt * 16 + r;
#pragma unroll
        for (int nt = 0; nt < 8; nt++) {
            const int n0 = ctaN + warpN * 64 + nt * 8 + 2 * c;
            const float bv0 = __ldg(&bias[n0]);
            const float bv1 = __ldg(&bias[n0 + 1]);
            float v0 = fmaxf(acc[mt][nt][0] + bv0, 0.0f);
            float v1 = fmaxf(acc[mt][nt][1] + bv1, 0.0f);
            float v2 = fmaxf(acc[mt][nt][2] + bv0, 0.0f);
            float v3 = fmaxf(acc[mt][nt][3] + bv1, 0.0f);
            *(float2*)&Out[(size_t)m0 * 256 + n0]       = make_float2(v0, v1);
            *(float2*)&Out[(size_t)(m0 + 8) * 256 + n0] = make_float2(v2, v3);
        }
    }
}

extern "C" void kernel_launch(void* const* d_in, const int* in_sizes, int n_in,
                              void* d_out, int out_size)
{
    const float* x = (const float*)d_in[0];   // [131072, 256]
    const float* W = (const float*)d_in[1];   // [256, 256]
    const float* b = (const float*)d_in[2];   // [256]
    float* out = (float*)d_out;               // [131072, 256]

    cudaFuncSetAttribute(gemm_tf32_relu,
                         cudaFuncAttributeMaxDynamicSharedMemorySize, SMEM_BYTES);

    dim3 grid(131072 / BM, 256 / BN);  // (1024, 2)
    dim3 block(256);
    gemm_tf32_relu<<<grid, block, SMEM_BYTES>>>(x, W, b, out);
}